// round 2
// baseline (speedup 1.0000x reference)
#include <cuda_runtime.h>
#include <cuda_bf16.h>
#include <mma.h>

using namespace nvcuda;

#define N_NODES 100000
#define N_EDGESC 1600000
#define XDIM 1010
#define SUBJ 1000
#define H1 512
#define H2 256
#define DG 128

// ---------------- static device scratch (no allocations allowed) ----------------
__device__ float g_h[(size_t)N_NODES * H1];    // 204.8 MB fp32 hidden
__device__ float g_W23[H1 * DG];               // folded W2@Wg[:256], fp32
__device__ float g_c2[DG];                     // b2@Wg[:256]
__device__ float g_y[(size_t)N_NODES * DG];    // dinv * xt
__device__ float g_s[(size_t)N_NODES * DG];    // aggregation accumulator
__device__ int   g_deg[N_NODES];
__device__ double g_acc;

__device__ __forceinline__ void split_bf16(float v, __nv_bfloat16& hi, __nv_bfloat16& lo) {
    hi = __float2bfloat16(v);
    lo = __float2bfloat16(v - __bfloat162float(hi));
}

// ---------------- init ----------------
__global__ void k_init() {
    int i = blockIdx.x * blockDim.x + threadIdx.x;
    if (i < N_NODES) g_deg[i] = 1;  // self loop
    if (i == 0) g_acc = 0.0;
}

// ---------------- weight fold: W23 = W2 @ Wg[:256], c2 = b2 @ Wg[:256] ----------------
__global__ void k_pre(const float* __restrict__ W2, const float* __restrict__ Wg,
                      const float* __restrict__ b2) {
    int k = blockIdx.x;
    int j = threadIdx.x;  // 0..127
    if (k < H1) {
        __shared__ float row[H2];
        for (int m = j; m < H2; m += 128) row[m] = W2[k * H2 + m];
        __syncthreads();
        float acc = 0.f;
        #pragma unroll 4
        for (int m = 0; m < H2; m++) acc += row[m] * Wg[m * DG + j];
        g_W23[k * DG + j] = acc;
    } else {
        float acc = 0.f;
        for (int m = 0; m < H2; m++) acc += b2[m] * Wg[m * DG + j];
        g_c2[j] = acc;
    }
}

// ================= split-bf16 WMMA GEMM core pieces =================
// smem layout (bytes):
//   AsH @ 0      : 128 x 48 bf16 = 12288
//   AsL @ 12288  : 128 x 48 bf16 = 12288
//   BsH @ 24576  :  32 x 80 bf16 =  5120
//   BsL @ 29696  :  32 x 80 bf16 =  5120
//   total 34816; Cs (float 128x68 = 34816) reuses the same buffer in epilogue.

// ---------------- GEMM1: h = relu(x[:, :1000] @ W1 + b1) ----------------
__global__ __launch_bounds__(256) void k_gemm1(const float* __restrict__ x,
                                               const float* __restrict__ W1,
                                               const float* __restrict__ b1) {
    __shared__ __align__(128) char smbuf[34816];
    __nv_bfloat16 (*AsH)[48] = reinterpret_cast<__nv_bfloat16(*)[48]>(smbuf);
    __nv_bfloat16 (*AsL)[48] = reinterpret_cast<__nv_bfloat16(*)[48]>(smbuf + 12288);
    __nv_bfloat16 (*BsH)[80] = reinterpret_cast<__nv_bfloat16(*)[80]>(smbuf + 24576);
    __nv_bfloat16 (*BsL)[80] = reinterpret_cast<__nv_bfloat16(*)[80]>(smbuf + 29696);
    float (*Cs)[68] = reinterpret_cast<float(*)[68]>(smbuf);

    const int i0 = blockIdx.x * 128;
    const int n0 = blockIdx.y * 64;
    const int tid = threadIdx.x;
    const int wid = tid >> 5;
    const int warpM = wid & 3, warpN = wid >> 2;

    wmma::fragment<wmma::accumulator, 16, 16, 16, float> acc[2][2];
    #pragma unroll
    for (int m = 0; m < 2; m++)
        #pragma unroll
        for (int n = 0; n < 2; n++) wmma::fill_fragment(acc[m][n], 0.f);

    for (int kt = 0; kt < 32; kt++) {  // covers K=1000 (zero-padded to 1024)
        const int k0 = kt * 32;
        // A tile: 128 rows x 32 cols, fp32 -> split bf16
        {
            int r = tid >> 4;
            int c = (tid & 15) * 2;
            #pragma unroll
            for (int p = 0; p < 8; p++, r += 16) {
                int gi = i0 + r, gk = k0 + c;
                float2 v = make_float2(0.f, 0.f);
                if (gi < N_NODES && gk < SUBJ)
                    v = *reinterpret_cast<const float2*>(&x[(size_t)gi * XDIM + gk]);
                __nv_bfloat16 h0, l0, h1, l1;
                split_bf16(v.x, h0, l0);
                split_bf16(v.y, h1, l1);
                AsH[r][c] = h0; AsH[r][c + 1] = h1;
                AsL[r][c] = l0; AsL[r][c + 1] = l1;
            }
        }
        // B tile: 32 rows x 64 cols of W1 -> split bf16
        {
            int r = tid >> 5;
            int c = (tid & 31) * 2;
            #pragma unroll
            for (int p = 0; p < 4; p++, r += 8) {
                int gk = k0 + r;
                float2 v = make_float2(0.f, 0.f);
                if (gk < SUBJ)
                    v = *reinterpret_cast<const float2*>(&W1[(size_t)gk * H1 + n0 + c]);
                __nv_bfloat16 h0, l0, h1, l1;
                split_bf16(v.x, h0, l0);
                split_bf16(v.y, h1, l1);
                BsH[r][c] = h0; BsH[r][c + 1] = h1;
                BsL[r][c] = l0; BsL[r][c + 1] = l1;
            }
        }
        __syncthreads();
        #pragma unroll
        for (int kk = 0; kk < 32; kk += 16) {
            wmma::fragment<wmma::matrix_a, 16, 16, 16, __nv_bfloat16, wmma::row_major> afH[2], afL[2];
            wmma::fragment<wmma::matrix_b, 16, 16, 16, __nv_bfloat16, wmma::row_major> bfH[2], bfL[2];
            #pragma unroll
            for (int m = 0; m < 2; m++) {
                wmma::load_matrix_sync(afH[m], &AsH[warpM * 32 + m * 16][kk], 48);
                wmma::load_matrix_sync(afL[m], &AsL[warpM * 32 + m * 16][kk], 48);
            }
            #pragma unroll
            for (int n = 0; n < 2; n++) {
                wmma::load_matrix_sync(bfH[n], &BsH[kk][warpN * 32 + n * 16], 80);
                wmma::load_matrix_sync(bfL[n], &BsL[kk][warpN * 32 + n * 16], 80);
            }
            #pragma unroll
            for (int m = 0; m < 2; m++)
                #pragma unroll
                for (int n = 0; n < 2; n++) {
                    wmma::mma_sync(acc[m][n], afL[m], bfH[n], acc[m][n]);
                    wmma::mma_sync(acc[m][n], afH[m], bfL[n], acc[m][n]);
                    wmma::mma_sync(acc[m][n], afH[m], bfH[n], acc[m][n]);
                }
        }
        __syncthreads();
    }
    // epilogue: frags -> smem -> relu(+bias) -> fp32 global
    #pragma unroll
    for (int m = 0; m < 2; m++)
        #pragma unroll
        for (int n = 0; n < 2; n++)
            wmma::store_matrix_sync(&Cs[warpM * 32 + m * 16][warpN * 32 + n * 16],
                                    acc[m][n], 68, wmma::mem_row_major);
    __syncthreads();
    for (int idx = tid; idx < 128 * 64; idx += 256) {
        int r = idx >> 6, c = idx & 63;
        int gi = i0 + r;
        if (gi < N_NODES) {
            float v = Cs[r][c] + __ldg(&b1[n0 + c]);
            v = fmaxf(v, 0.f);
            g_h[(size_t)gi * H1 + n0 + c] = v;
        }
    }
}

// ---------------- degree count ----------------
__global__ void k_deg(const int* __restrict__ ei) {
    for (int e = blockIdx.x * blockDim.x + threadIdx.x; e < N_EDGESC;
         e += gridDim.x * blockDim.x) {
        int dst = ei[N_EDGESC + e];
        dst = min(max(dst, 0), N_NODES - 1);
        atomicAdd(&g_deg[dst], 1);
    }
}

// ---------------- GEMM2': xt = h @ W23 + demo @ Wg[256:] + c2 ; y = s = dinv*xt ----------------
__global__ __launch_bounds__(256) void k_gemm2(const float* __restrict__ x,
                                               const float* __restrict__ Wg) {
    __shared__ __align__(128) char smbuf[34816];
    __nv_bfloat16 (*AsH)[48] = reinterpret_cast<__nv_bfloat16(*)[48]>(smbuf);
    __nv_bfloat16 (*AsL)[48] = reinterpret_cast<__nv_bfloat16(*)[48]>(smbuf + 12288);
    __nv_bfloat16 (*BsH)[80] = reinterpret_cast<__nv_bfloat16(*)[80]>(smbuf + 24576);
    __nv_bfloat16 (*BsL)[80] = reinterpret_cast<__nv_bfloat16(*)[80]>(smbuf + 29696);
    float (*Cs)[68] = reinterpret_cast<float(*)[68]>(smbuf);
    __shared__ float demoS[128][10];
    __shared__ float WgbS[10][64];
    __shared__ float c2S[64];

    const int i0 = blockIdx.x * 128;
    const int n0 = blockIdx.y * 64;
    const int tid = threadIdx.x;
    const int wid = tid >> 5;
    const int warpM = wid & 3, warpN = wid >> 2;

    // stage demo / Wg-bottom / c2
    for (int idx = tid; idx < 128 * 10; idx += 256) {
        int r = idx / 10, t = idx % 10;
        int gi = i0 + r;
        demoS[r][t] = (gi < N_NODES) ? x[(size_t)gi * XDIM + SUBJ + t] : 0.f;
    }
    for (int idx = tid; idx < 10 * 64; idx += 256) {
        int t = idx >> 6, c = idx & 63;
        WgbS[t][c] = Wg[(H2 + t) * DG + n0 + c];
    }
    if (tid < 64) c2S[tid] = g_c2[n0 + tid];

    wmma::fragment<wmma::accumulator, 16, 16, 16, float> acc[2][2];
    #pragma unroll
    for (int m = 0; m < 2; m++)
        #pragma unroll
        for (int n = 0; n < 2; n++) wmma::fill_fragment(acc[m][n], 0.f);

    for (int kt = 0; kt < 16; kt++) {  // K = 512 exact
        const int k0 = kt * 32;
        // A tile from g_h (fp32): 128x32, split
        {
            int r = tid >> 4;
            int c = (tid & 15) * 2;
            #pragma unroll
            for (int p = 0; p < 8; p++, r += 16) {
                int gi = i0 + r;
                float2 v = make_float2(0.f, 0.f);
                if (gi < N_NODES)
                    v = *reinterpret_cast<const float2*>(&g_h[(size_t)gi * H1 + k0 + c]);
                __nv_bfloat16 h0, l0, h1, l1;
                split_bf16(v.x, h0, l0);
                split_bf16(v.y, h1, l1);
                AsH[r][c] = h0; AsH[r][c + 1] = h1;
                AsL[r][c] = l0; AsL[r][c + 1] = l1;
            }
        }
        // B tile from g_W23 (fp32): 32x64, split
        {
            int r = tid >> 5;
            int c = (tid & 31) * 2;
            #pragma unroll
            for (int p = 0; p < 4; p++, r += 8) {
                float2 v = *reinterpret_cast<const float2*>(&g_W23[(k0 + r) * DG + n0 + c]);
                __nv_bfloat16 h0, l0, h1, l1;
                split_bf16(v.x, h0, l0);
                split_bf16(v.y, h1, l1);
                BsH[r][c] = h0; BsH[r][c + 1] = h1;
                BsL[r][c] = l0; BsL[r][c + 1] = l1;
            }
        }
        __syncthreads();
        #pragma unroll
        for (int kk = 0; kk < 32; kk += 16) {
            wmma::fragment<wmma::matrix_a, 16, 16, 16, __nv_bfloat16, wmma::row_major> afH[2], afL[2];
            wmma::fragment<wmma::matrix_b, 16, 16, 16, __nv_bfloat16, wmma::row_major> bfH[2], bfL[2];
            #pragma unroll
            for (int m = 0; m < 2; m++) {
                wmma::load_matrix_sync(afH[m], &AsH[warpM * 32 + m * 16][kk], 48);
                wmma::load_matrix_sync(afL[m], &AsL[warpM * 32 + m * 16][kk], 48);
            }
            #pragma unroll
            for (int n = 0; n < 2; n++) {
                wmma::load_matrix_sync(bfH[n], &BsH[kk][warpN * 32 + n * 16], 80);
                wmma::load_matrix_sync(bfL[n], &BsL[kk][warpN * 32 + n * 16], 80);
            }
            #pragma unroll
            for (int m = 0; m < 2; m++)
                #pragma unroll
                for (int n = 0; n < 2; n++) {
                    wmma::mma_sync(acc[m][n], afL[m], bfH[n], acc[m][n]);
                    wmma::mma_sync(acc[m][n], afH[m], bfL[n], acc[m][n]);
                    wmma::mma_sync(acc[m][n], afH[m], bfH[n], acc[m][n]);
                }
        }
        __syncthreads();
    }
    #pragma unroll
    for (int m = 0; m < 2; m++)
        #pragma unroll
        for (int n = 0; n < 2; n++)
            wmma::store_matrix_sync(&Cs[warpM * 32 + m * 16][warpN * 32 + n * 16],
                                    acc[m][n], 68, wmma::mem_row_major);
    __syncthreads();
    for (int idx = tid; idx < 128 * 64; idx += 256) {
        int r = idx >> 6, c = idx & 63;
        int gi = i0 + r;
        if (gi < N_NODES) {
            float v = Cs[r][c] + c2S[c];
            #pragma unroll
            for (int t = 0; t < 10; t++) v += demoS[r][t] * WgbS[t][c];
            float dinv = rsqrtf((float)g_deg[gi]);
            float yv = dinv * v;
            size_t o = (size_t)gi * DG + n0 + c;
            g_y[o] = yv;
            g_s[o] = yv;  // self-loop seed
        }
    }
}

// ---------------- edge scatter: s[dst] += y[src], one warp per edge ----------------
__global__ __launch_bounds__(256) void k_scatter(const int* __restrict__ ei) {
    int gw = (blockIdx.x * blockDim.x + threadIdx.x) >> 5;
    if (gw >= N_EDGESC) return;
    int lane = threadIdx.x & 31;
    int src = __ldg(&ei[gw]);
    int dst = __ldg(&ei[N_EDGESC + gw]);
    src = min(max(src, 0), N_NODES - 1);
    dst = min(max(dst, 0), N_NODES - 1);
    float4 v = *reinterpret_cast<const float4*>(&g_y[(size_t)src * DG + lane * 4]);
    float* sp = &g_s[(size_t)dst * DG + lane * 4];
    atomicAdd(sp + 0, v.x);
    atomicAdd(sp + 1, v.y);
    atomicAdd(sp + 2, v.z);
    atomicAdd(sp + 3, v.w);
}

// ---------------- final reduce: sum_i relu(dinv*s + bg) . Wo ----------------
__global__ __launch_bounds__(256) void k_reduce(const float* __restrict__ bg,
                                                const float* __restrict__ Wo) {
    int wid = threadIdx.x >> 5, lane = threadIdx.x & 31;
    int node = blockIdx.x * 8 + wid;
    float acc = 0.f;
    if (node < N_NODES) {
        float dinv = rsqrtf((float)g_deg[node]);
        float4 sv = *reinterpret_cast<const float4*>(&g_s[(size_t)node * DG + lane * 4]);
        float4 bgv = *reinterpret_cast<const float4*>(&bg[lane * 4]);
        float4 wv = *reinterpret_cast<const float4*>(&Wo[lane * 4]);
        acc += fmaxf(dinv * sv.x + bgv.x, 0.f) * wv.x;
        acc += fmaxf(dinv * sv.y + bgv.y, 0.f) * wv.y;
        acc += fmaxf(dinv * sv.z + bgv.z, 0.f) * wv.z;
        acc += fmaxf(dinv * sv.w + bgv.w, 0.f) * wv.w;
    }
    #pragma unroll
    for (int o = 16; o; o >>= 1) acc += __shfl_down_sync(0xffffffffu, acc, o);
    __shared__ float part[8];
    if (lane == 0) part[wid] = acc;
    __syncthreads();
    if (threadIdx.x == 0) {
        float s = 0.f;
        #pragma unroll
        for (int w = 0; w < 8; w++) s += part[w];
        atomicAdd(&g_acc, (double)s);
    }
}

__global__ void k_fin(const float* __restrict__ bo, float* __restrict__ out) {
    out[0] = (float)(g_acc * (1.0 / (double)N_NODES) + (double)bo[0]);
}

// ---------------- launch ----------------
extern "C" void kernel_launch(void* const* d_in, const int* in_sizes, int n_in,
                              void* d_out, int out_size) {
    const float* x  = (const float*)d_in[0];
    const int*   ei = (const int*)d_in[1];   // jax x64 disabled -> int32
    const float* W1 = (const float*)d_in[2];
    const float* b1 = (const float*)d_in[3];
    const float* W2 = (const float*)d_in[4];
    const float* b2 = (const float*)d_in[5];
    const float* Wg = (const float*)d_in[6];
    const float* bg = (const float*)d_in[7];
    const float* Wo = (const float*)d_in[8];
    const float* bo = (const float*)d_in[9];
    float* out = (float*)d_out;

    k_init<<<(N_NODES + 255) / 256, 256>>>();
    k_pre<<<H1 + 1, 128>>>(W2, Wg, b2);
    k_gemm1<<<dim3((N_NODES + 127) / 128, H1 / 64), 256>>>(x, W1, b1);
    k_deg<<<4096, 256>>>(ei);
    k_gemm2<<<dim3((N_NODES + 127) / 128, DG / 64), 256>>>(x, Wg);
    {
        long long threads = (long long)N_EDGESC * 32;
        int blocks = (int)((threads + 255) / 256);
        k_scatter<<<blocks, 256>>>(ei);
    }
    k_reduce<<<(N_NODES + 7) / 8, 256>>>(bg, Wo);
    k_fin<<<1, 1>>>(bo, out);
}

// round 3
// speedup vs baseline: 1.1850x; 1.1850x over previous
#include <cuda_runtime.h>
#include <cuda_bf16.h>
#include <mma.h>

using namespace nvcuda;

#define N_NODES 100000
#define N_EDGESC 1600000
#define XDIM 1010
#define SUBJ 1000
#define H1 512
#define H2 256
#define DG 128

// smem tile geometry (bf16 elems)
#define LDA 40     // 32 + 8  (80B rows, mult of 16B, conflict-free)
#define LDB 136    // 128 + 8 (272B rows)
#define LDC 136
#define SZ_AH (128 * LDA * 2)        // 10240 B
#define SZ_BH (32 * LDB * 2)         // 8704 B
#define OFF_AL SZ_AH                 // 10240
#define OFF_BH (2 * SZ_AH)           // 20480
#define OFF_BL (2 * SZ_AH + SZ_BH)   // 29184
#define STAGE_BYTES (2 * SZ_AH + 2 * SZ_BH)  // 37888
#define DYN_BYTES (2 * STAGE_BYTES)          // 75776

// ---------------- static device scratch ----------------
__device__ float g_h[(size_t)N_NODES * H1];    // fp32 hidden, 204.8 MB
__device__ float g_W23[H1 * DG];               // folded W2@Wg[:256]
__device__ float g_c2[DG];                     // b2@Wg[:256]
__device__ float g_y[(size_t)N_NODES * DG];    // dinv * xt
__device__ int   g_deg[N_NODES];               // degree incl self-loop
__device__ int   g_off[N_NODES];               // CSR offsets (edges only)
__device__ int   g_cur[N_NODES];
__device__ int   g_es[N_EDGESC];               // srcs sorted by dst
__device__ double g_acc;

__device__ __forceinline__ void split_bf16(float v, __nv_bfloat16& hi, __nv_bfloat16& lo) {
    hi = __float2bfloat16(v);
    lo = __float2bfloat16(v - __bfloat162float(hi));
}

// ---------------- init ----------------
__global__ void k_init() {
    int i = blockIdx.x * blockDim.x + threadIdx.x;
    if (i < N_NODES) g_deg[i] = 1;
    if (i == 0) g_acc = 0.0;
}

// ---------------- weight fold ----------------
__global__ void k_pre(const float* __restrict__ W2, const float* __restrict__ Wg,
                      const float* __restrict__ b2) {
    int k = blockIdx.x;
    int j = threadIdx.x;  // 0..127
    if (k < H1) {
        __shared__ float row[H2];
        for (int m = j; m < H2; m += 128) row[m] = W2[k * H2 + m];
        __syncthreads();
        float acc = 0.f;
        #pragma unroll 4
        for (int m = 0; m < H2; m++) acc += row[m] * Wg[m * DG + j];
        g_W23[k * DG + j] = acc;
    } else {
        float acc = 0.f;
        for (int m = 0; m < H2; m++) acc += b2[m] * Wg[m * DG + j];
        g_c2[j] = acc;
    }
}

// ---------------- degree count ----------------
__global__ void k_deg(const int* __restrict__ ei) {
    for (int e = blockIdx.x * blockDim.x + threadIdx.x; e < N_EDGESC;
         e += gridDim.x * blockDim.x) {
        int dst = ei[N_EDGESC + e];
        dst = min(max(dst, 0), N_NODES - 1);
        atomicAdd(&g_deg[dst], 1);
    }
}

// ---------------- exclusive scan of (deg-1): single block, 1024 threads ----------------
__global__ void k_scan() {
    __shared__ int warpTot[32];
    __shared__ int base;
    int lane = threadIdx.x & 31, wid = threadIdx.x >> 5;
    if (threadIdx.x == 0) base = 0;
    __syncthreads();
    for (int start = 0; start < N_NODES; start += 1024) {
        int i = start + threadIdx.x;
        int v = (i < N_NODES) ? (g_deg[i] - 1) : 0;
        int s = v;
        #pragma unroll
        for (int o = 1; o < 32; o <<= 1) {
            int t = __shfl_up_sync(0xffffffffu, s, o);
            if (lane >= o) s += t;
        }
        if (lane == 31) warpTot[wid] = s;
        __syncthreads();
        if (wid == 0) {
            int t = warpTot[lane];
            #pragma unroll
            for (int o = 1; o < 32; o <<= 1) {
                int u = __shfl_up_sync(0xffffffffu, t, o);
                if (lane >= o) t += u;
            }
            warpTot[lane] = t;
        }
        __syncthreads();
        int excl = s - v + (wid > 0 ? warpTot[wid - 1] : 0) + base;
        if (i < N_NODES) { g_off[i] = excl; g_cur[i] = excl; }
        __syncthreads();
        if (threadIdx.x == 0) base += warpTot[31];
        __syncthreads();
    }
}

// ---------------- CSR fill ----------------
__global__ void k_fill(const int* __restrict__ ei) {
    for (int e = blockIdx.x * blockDim.x + threadIdx.x; e < N_EDGESC;
         e += gridDim.x * blockDim.x) {
        int src = ei[e];
        int dst = ei[N_EDGESC + e];
        src = min(max(src, 0), N_NODES - 1);
        dst = min(max(dst, 0), N_NODES - 1);
        int pos = atomicAdd(&g_cur[dst], 1);
        g_es[pos] = src;
    }
}

// ================= GEMM1: h = relu(x[:, :1000] @ W1 + b1) =================
// BM=128 BN=128 BK=32, double-buffered, 8 warps 4(M)x2(N), warp tile 32x64
__global__ __launch_bounds__(256) void k_gemm1(const float* __restrict__ x,
                                               const float* __restrict__ W1,
                                               const float* __restrict__ b1) {
    extern __shared__ __align__(128) char dyn[];
    const int i0 = blockIdx.x * 128;
    const int n0 = blockIdx.y * 128;
    const int tid = threadIdx.x;
    const int wid = tid >> 5;
    const int warpM = wid & 3, warpN = wid >> 2;

    // load mappings
    const int arow = tid >> 4;            // 0..15
    const int acol = (tid & 15) * 2;      // 0..30
    const int brow = tid >> 6;            // 0..3
    const int bcol = (tid & 63) * 2;      // 0..126

    wmma::fragment<wmma::accumulator, 16, 16, 16, float> acc[2][4];
    #pragma unroll
    for (int m = 0; m < 2; m++)
        #pragma unroll
        for (int n = 0; n < 4; n++) wmma::fill_fragment(acc[m][n], 0.f);

    float2 aR[8], bR[8];

    // ---- prologue: load kt=0 ----
    {
        const int k0 = 0;
        #pragma unroll
        for (int p = 0; p < 8; p++) {
            int gi = i0 + arow + p * 16, gk = k0 + acol;
            aR[p] = (gi < N_NODES && gk < SUBJ)
                ? *reinterpret_cast<const float2*>(&x[(size_t)gi * XDIM + gk])
                : make_float2(0.f, 0.f);
        }
        #pragma unroll
        for (int p = 0; p < 8; p++) {
            int gk = k0 + brow + p * 4;
            bR[p] = (gk < SUBJ)
                ? *reinterpret_cast<const float2*>(&W1[(size_t)gk * H1 + n0 + bcol])
                : make_float2(0.f, 0.f);
        }
    }
    // store stage 0
    {
        char* st = dyn;
        __nv_bfloat16 (*AsH)[LDA] = reinterpret_cast<__nv_bfloat16(*)[LDA]>(st);
        __nv_bfloat16 (*AsL)[LDA] = reinterpret_cast<__nv_bfloat16(*)[LDA]>(st + OFF_AL);
        __nv_bfloat16 (*BsH)[LDB] = reinterpret_cast<__nv_bfloat16(*)[LDB]>(st + OFF_BH);
        __nv_bfloat16 (*BsL)[LDB] = reinterpret_cast<__nv_bfloat16(*)[LDB]>(st + OFF_BL);
        #pragma unroll
        for (int p = 0; p < 8; p++) {
            int r = arow + p * 16;
            __nv_bfloat16 h0, l0, h1, l1;
            split_bf16(aR[p].x, h0, l0); split_bf16(aR[p].y, h1, l1);
            AsH[r][acol] = h0; AsH[r][acol + 1] = h1;
            AsL[r][acol] = l0; AsL[r][acol + 1] = l1;
        }
        #pragma unroll
        for (int p = 0; p < 8; p++) {
            int r = brow + p * 4;
            __nv_bfloat16 h0, l0, h1, l1;
            split_bf16(bR[p].x, h0, l0); split_bf16(bR[p].y, h1, l1);
            BsH[r][bcol] = h0; BsH[r][bcol + 1] = h1;
            BsL[r][bcol] = l0; BsL[r][bcol + 1] = l1;
        }
    }
    __syncthreads();

    for (int kt = 0; kt < 32; kt++) {
        const int cur = kt & 1;
        // prefetch next tile into regs
        if (kt + 1 < 32) {
            const int k0 = (kt + 1) * 32;
            #pragma unroll
            for (int p = 0; p < 8; p++) {
                int gi = i0 + arow + p * 16, gk = k0 + acol;
                aR[p] = (gi < N_NODES && gk < SUBJ)
                    ? *reinterpret_cast<const float2*>(&x[(size_t)gi * XDIM + gk])
                    : make_float2(0.f, 0.f);
            }
            #pragma unroll
            for (int p = 0; p < 8; p++) {
                int gk = k0 + brow + p * 4;
                bR[p] = (gk < SUBJ)
                    ? *reinterpret_cast<const float2*>(&W1[(size_t)gk * H1 + n0 + bcol])
                    : make_float2(0.f, 0.f);
            }
        }
        // MMA on stage cur
        {
            char* st = dyn + cur * STAGE_BYTES;
            __nv_bfloat16 (*AsH)[LDA] = reinterpret_cast<__nv_bfloat16(*)[LDA]>(st);
            __nv_bfloat16 (*AsL)[LDA] = reinterpret_cast<__nv_bfloat16(*)[LDA]>(st + OFF_AL);
            __nv_bfloat16 (*BsH)[LDB] = reinterpret_cast<__nv_bfloat16(*)[LDB]>(st + OFF_BH);
            __nv_bfloat16 (*BsL)[LDB] = reinterpret_cast<__nv_bfloat16(*)[LDB]>(st + OFF_BL);
            #pragma unroll
            for (int kk = 0; kk < 32; kk += 16) {
                wmma::fragment<wmma::matrix_a, 16, 16, 16, __nv_bfloat16, wmma::row_major> afH[2], afL[2];
                #pragma unroll
                for (int m = 0; m < 2; m++) {
                    wmma::load_matrix_sync(afH[m], &AsH[warpM * 32 + m * 16][kk], LDA);
                    wmma::load_matrix_sync(afL[m], &AsL[warpM * 32 + m * 16][kk], LDA);
                }
                #pragma unroll
                for (int n = 0; n < 4; n++) {
                    wmma::fragment<wmma::matrix_b, 16, 16, 16, __nv_bfloat16, wmma::row_major> bfH, bfL;
                    wmma::load_matrix_sync(bfH, &BsH[kk][warpN * 64 + n * 16], LDB);
                    wmma::load_matrix_sync(bfL, &BsL[kk][warpN * 64 + n * 16], LDB);
                    #pragma unroll
                    for (int m = 0; m < 2; m++) {
                        wmma::mma_sync(acc[m][n], afL[m], bfH, acc[m][n]);
                        wmma::mma_sync(acc[m][n], afH[m], bfL, acc[m][n]);
                        wmma::mma_sync(acc[m][n], afH[m], bfH, acc[m][n]);
                    }
                }
            }
        }
        // store next stage
        if (kt + 1 < 32) {
            char* st = dyn + (cur ^ 1) * STAGE_BYTES;
            __nv_bfloat16 (*AsH)[LDA] = reinterpret_cast<__nv_bfloat16(*)[LDA]>(st);
            __nv_bfloat16 (*AsL)[LDA] = reinterpret_cast<__nv_bfloat16(*)[LDA]>(st + OFF_AL);
            __nv_bfloat16 (*BsH)[LDB] = reinterpret_cast<__nv_bfloat16(*)[LDB]>(st + OFF_BH);
            __nv_bfloat16 (*BsL)[LDB] = reinterpret_cast<__nv_bfloat16(*)[LDB]>(st + OFF_BL);
            #pragma unroll
            for (int p = 0; p < 8; p++) {
                int r = arow + p * 16;
                __nv_bfloat16 h0, l0, h1, l1;
                split_bf16(aR[p].x, h0, l0); split_bf16(aR[p].y, h1, l1);
                AsH[r][acol] = h0; AsH[r][acol + 1] = h1;
                AsL[r][acol] = l0; AsL[r][acol + 1] = l1;
            }
            #pragma unroll
            for (int p = 0; p < 8; p++) {
                int r = brow + p * 4;
                __nv_bfloat16 h0, l0, h1, l1;
                split_bf16(bR[p].x, h0, l0); split_bf16(bR[p].y, h1, l1);
                BsH[r][bcol] = h0; BsH[r][bcol + 1] = h1;
                BsL[r][bcol] = l0; BsL[r][bcol + 1] = l1;
            }
            __syncthreads();
        }
    }

    // epilogue via smem (reuse dynamic buffer)
    __syncthreads();
    float (*Cs)[LDC] = reinterpret_cast<float(*)[LDC]>(dyn);
    #pragma unroll
    for (int m = 0; m < 2; m++)
        #pragma unroll
        for (int n = 0; n < 4; n++)
            wmma::store_matrix_sync(&Cs[warpM * 32 + m * 16][warpN * 64 + n * 16],
                                    acc[m][n], LDC, wmma::mem_row_major);
    __syncthreads();
    #pragma unroll
    for (int q = 0; q < 64; q++) {
        int idx = q * 256 + tid;
        int r = idx >> 7, c = idx & 127;
        int gi = i0 + r;
        if (gi < N_NODES) {
            float v = Cs[r][c] + __ldg(&b1[n0 + c]);
            g_h[(size_t)gi * H1 + n0 + c] = fmaxf(v, 0.f);
        }
    }
}

// ================= GEMM2': y = dinv*(h @ W23 + demo @ Wg[256:] + c2) =================
__global__ __launch_bounds__(256) void k_gemm2(const float* __restrict__ x,
                                               const float* __restrict__ Wg) {
    extern __shared__ __align__(128) char dyn[];
    __shared__ float demoS[128][10];
    __shared__ float WgbS[10][DG];
    __shared__ float c2S[DG];

    const int i0 = blockIdx.x * 128;
    const int tid = threadIdx.x;
    const int wid = tid >> 5;
    const int warpM = wid & 3, warpN = wid >> 2;

    for (int idx = tid; idx < 128 * 10; idx += 256) {
        int r = idx / 10, t = idx % 10;
        int gi = i0 + r;
        demoS[r][t] = (gi < N_NODES) ? x[(size_t)gi * XDIM + SUBJ + t] : 0.f;
    }
    for (int idx = tid; idx < 10 * DG; idx += 256) {
        int t = idx >> 7, c = idx & 127;
        WgbS[t][c] = Wg[(H2 + t) * DG + c];
    }
    if (tid < DG) c2S[tid] = g_c2[tid];

    const int arow = tid >> 4;
    const int acol = (tid & 15) * 2;
    const int brow = tid >> 6;
    const int bcol = (tid & 63) * 2;

    wmma::fragment<wmma::accumulator, 16, 16, 16, float> acc[2][4];
    #pragma unroll
    for (int m = 0; m < 2; m++)
        #pragma unroll
        for (int n = 0; n < 4; n++) wmma::fill_fragment(acc[m][n], 0.f);

    float2 aR[8], bR[8];
    {
        #pragma unroll
        for (int p = 0; p < 8; p++) {
            int gi = i0 + arow + p * 16;
            aR[p] = (gi < N_NODES)
                ? *reinterpret_cast<const float2*>(&g_h[(size_t)gi * H1 + acol])
                : make_float2(0.f, 0.f);
        }
        #pragma unroll
        for (int p = 0; p < 8; p++)
            bR[p] = *reinterpret_cast<const float2*>(&g_W23[(brow + p * 4) * DG + bcol]);
    }
    {
        char* st = dyn;
        __nv_bfloat16 (*AsH)[LDA] = reinterpret_cast<__nv_bfloat16(*)[LDA]>(st);
        __nv_bfloat16 (*AsL)[LDA] = reinterpret_cast<__nv_bfloat16(*)[LDA]>(st + OFF_AL);
        __nv_bfloat16 (*BsH)[LDB] = reinterpret_cast<__nv_bfloat16(*)[LDB]>(st + OFF_BH);
        __nv_bfloat16 (*BsL)[LDB] = reinterpret_cast<__nv_bfloat16(*)[LDB]>(st + OFF_BL);
        #pragma unroll
        for (int p = 0; p < 8; p++) {
            int r = arow + p * 16;
            __nv_bfloat16 h0, l0, h1, l1;
            split_bf16(aR[p].x, h0, l0); split_bf16(aR[p].y, h1, l1);
            AsH[r][acol] = h0; AsH[r][acol + 1] = h1;
            AsL[r][acol] = l0; AsL[r][acol + 1] = l1;
        }
        #pragma unroll
        for (int p = 0; p < 8; p++) {
            int r = brow + p * 4;
            __nv_bfloat16 h0, l0, h1, l1;
            split_bf16(bR[p].x, h0, l0); split_bf16(bR[p].y, h1, l1);
            BsH[r][bcol] = h0; BsH[r][bcol + 1] = h1;
            BsL[r][bcol] = l0; BsL[r][bcol + 1] = l1;
        }
    }
    __syncthreads();

    for (int kt = 0; kt < 16; kt++) {
        const int cur = kt & 1;
        if (kt + 1 < 16) {
            const int k0 = (kt + 1) * 32;
            #pragma unroll
            for (int p = 0; p < 8; p++) {
                int gi = i0 + arow + p * 16;
                aR[p] = (gi < N_NODES)
                    ? *reinterpret_cast<const float2*>(&g_h[(size_t)gi * H1 + k0 + acol])
                    : make_float2(0.f, 0.f);
            }
            #pragma unroll
            for (int p = 0; p < 8; p++)
                bR[p] = *reinterpret_cast<const float2*>(&g_W23[(k0 + brow + p * 4) * DG + bcol]);
        }
        {
            char* st = dyn + cur * STAGE_BYTES;
            __nv_bfloat16 (*AsH)[LDA] = reinterpret_cast<__nv_bfloat16(*)[LDA]>(st);
            __nv_bfloat16 (*AsL)[LDA] = reinterpret_cast<__nv_bfloat16(*)[LDA]>(st + OFF_AL);
            __nv_bfloat16 (*BsH)[LDB] = reinterpret_cast<__nv_bfloat16(*)[LDB]>(st + OFF_BH);
            __nv_bfloat16 (*BsL)[LDB] = reinterpret_cast<__nv_bfloat16(*)[LDB]>(st + OFF_BL);
            #pragma unroll
            for (int kk = 0; kk < 32; kk += 16) {
                wmma::fragment<wmma::matrix_a, 16, 16, 16, __nv_bfloat16, wmma::row_major> afH[2], afL[2];
                #pragma unroll
                for (int m = 0; m < 2; m++) {
                    wmma::load_matrix_sync(afH[m], &AsH[warpM * 32 + m * 16][kk], LDA);
                    wmma::load_matrix_sync(afL[m], &AsL[warpM * 32 + m * 16][kk], LDA);
                }
                #pragma unroll
                for (int n = 0; n < 4; n++) {
                    wmma::fragment<wmma::matrix_b, 16, 16, 16, __nv_bfloat16, wmma::row_major> bfH, bfL;
                    wmma::load_matrix_sync(bfH, &BsH[kk][warpN * 64 + n * 16], LDB);
                    wmma::load_matrix_sync(bfL, &BsL[kk][warpN * 64 + n * 16], LDB);
                    #pragma unroll
                    for (int m = 0; m < 2; m++) {
                        wmma::mma_sync(acc[m][n], afL[m], bfH, acc[m][n]);
                        wmma::mma_sync(acc[m][n], afH[m], bfL, acc[m][n]);
                        wmma::mma_sync(acc[m][n], afH[m], bfH, acc[m][n]);
                    }
                }
            }
        }
        if (kt + 1 < 16) {
            char* st = dyn + (cur ^ 1) * STAGE_BYTES;
            __nv_bfloat16 (*AsH)[LDA] = reinterpret_cast<__nv_bfloat16(*)[LDA]>(st);
            __nv_bfloat16 (*AsL)[LDA] = reinterpret_cast<__nv_bfloat16(*)[LDA]>(st + OFF_AL);
            __nv_bfloat16 (*BsH)[LDB] = reinterpret_cast<__nv_bfloat16(*)[LDB]>(st + OFF_BH);
            __nv_bfloat16 (*BsL)[LDB] = reinterpret_cast<__nv_bfloat16(*)[LDB]>(st + OFF_BL);
            #pragma unroll
            for (int p = 0; p < 8; p++) {
                int r = arow + p * 16;
                __nv_bfloat16 h0, l0, h1, l1;
                split_bf16(aR[p].x, h0, l0); split_bf16(aR[p].y, h1, l1);
                AsH[r][acol] = h0; AsH[r][acol + 1] = h1;
                AsL[r][acol] = l0; AsL[r][acol + 1] = l1;
            }
            #pragma unroll
            for (int p = 0; p < 8; p++) {
                int r = brow + p * 4;
                __nv_bfloat16 h0, l0, h1, l1;
                split_bf16(bR[p].x, h0, l0); split_bf16(bR[p].y, h1, l1);
                BsH[r][bcol] = h0; BsH[r][bcol + 1] = h1;
                BsL[r][bcol] = l0; BsL[r][bcol + 1] = l1;
            }
            __syncthreads();
        }
    }

    __syncthreads();
    float (*Cs)[LDC] = reinterpret_cast<float(*)[LDC]>(dyn);
    #pragma unroll
    for (int m = 0; m < 2; m++)
        #pragma unroll
        for (int n = 0; n < 4; n++)
            wmma::store_matrix_sync(&Cs[warpM * 32 + m * 16][warpN * 64 + n * 16],
                                    acc[m][n], LDC, wmma::mem_row_major);
    __syncthreads();
    #pragma unroll
    for (int q = 0; q < 64; q++) {
        int idx = q * 256 + tid;
        int r = idx >> 7, c = idx & 127;
        int gi = i0 + r;
        if (gi < N_NODES) {
            float v = Cs[r][c] + c2S[c];
            #pragma unroll
            for (int t = 0; t < 10; t++) v += demoS[r][t] * WgbS[t][c];
            float dinv = rsqrtf((float)g_deg[gi]);
            g_y[(size_t)gi * DG + c] = dinv * v;
        }
    }
}

// ---------------- gather + fused epilogue: one warp per node ----------------
__global__ __launch_bounds__(256) void k_gather(const float* __restrict__ bg,
                                                const float* __restrict__ Wo) {
    int wid = threadIdx.x >> 5, lane = threadIdx.x & 31;
    int node = blockIdx.x * 8 + wid;
    float dot = 0.f;
    if (node < N_NODES) {
        int deg = g_deg[node];
        int beg = g_off[node];
        int cnt = deg - 1;
        float4 a = *reinterpret_cast<const float4*>(&g_y[(size_t)node * DG + lane * 4]);
        #pragma unroll 4
        for (int j = 0; j < cnt; j++) {
            int s = __ldg(&g_es[beg + j]);
            float4 v = *reinterpret_cast<const float4*>(&g_y[(size_t)s * DG + lane * 4]);
            a.x += v.x; a.y += v.y; a.z += v.z; a.w += v.w;
        }
        float dinv = rsqrtf((float)deg);
        float4 bgv = *reinterpret_cast<const float4*>(&bg[lane * 4]);
        float4 wv = *reinterpret_cast<const float4*>(&Wo[lane * 4]);
        dot += fmaxf(dinv * a.x + bgv.x, 0.f) * wv.x;
        dot += fmaxf(dinv * a.y + bgv.y, 0.f) * wv.y;
        dot += fmaxf(dinv * a.z + bgv.z, 0.f) * wv.z;
        dot += fmaxf(dinv * a.w + bgv.w, 0.f) * wv.w;
    }
    #pragma unroll
    for (int o = 16; o; o >>= 1) dot += __shfl_down_sync(0xffffffffu, dot, o);
    __shared__ float part[8];
    if (lane == 0) part[wid] = dot;
    __syncthreads();
    if (threadIdx.x == 0) {
        float s = 0.f;
        #pragma unroll
        for (int w = 0; w < 8; w++) s += part[w];
        atomicAdd(&g_acc, (double)s);
    }
}

__global__ void k_fin(const float* __restrict__ bo, float* __restrict__ out) {
    out[0] = (float)(g_acc * (1.0 / (double)N_NODES) + (double)bo[0]);
}

// ---------------- launch ----------------
extern "C" void kernel_launch(void* const* d_in, const int* in_sizes, int n_in,
                              void* d_out, int out_size) {
    const float* x  = (const float*)d_in[0];
    const int*   ei = (const int*)d_in[1];
    const float* W1 = (const float*)d_in[2];
    const float* b1 = (const float*)d_in[3];
    const float* W2 = (const float*)d_in[4];
    const float* b2 = (const float*)d_in[5];
    const float* Wg = (const float*)d_in[6];
    const float* bg = (const float*)d_in[7];
    const float* Wo = (const float*)d_in[8];
    const float* bo = (const float*)d_in[9];
    float* out = (float*)d_out;

    cudaFuncSetAttribute(k_gemm1, cudaFuncAttributeMaxDynamicSharedMemorySize, DYN_BYTES);
    cudaFuncSetAttribute(k_gemm2, cudaFuncAttributeMaxDynamicSharedMemorySize, DYN_BYTES);

    k_init<<<(N_NODES + 255) / 256, 256>>>();
    k_pre<<<H1 + 1, 128>>>(W2, Wg, b2);
    k_deg<<<4096, 256>>>(ei);
    k_scan<<<1, 1024>>>();
    k_fill<<<4096, 256>>>(ei);
    k_gemm1<<<dim3((N_NODES + 127) / 128, H1 / 128), 256, DYN_BYTES>>>(x, W1, b1);
    k_gemm2<<<(N_NODES + 127) / 128, 256, DYN_BYTES>>>(x, Wg);
    k_gather<<<(N_NODES + 7) / 8, 256>>>(bg, Wo);
    k_fin<<<1, 1>>>(bo, out);
}

// round 5
// speedup vs baseline: 1.9996x; 1.6874x over previous
#include <cuda_runtime.h>
#include <cuda_fp16.h>
#include <mma.h>
#include <cstdint>

using namespace nvcuda;

#define N_NODES 100000
#define N_EDGESC 1600000
#define XDIM 1010
#define SUBJ 1000
#define H1 512
#define H2 256
#define DG 128

// ---------------- static device scratch ----------------
__device__ __half g_xs[(size_t)N_NODES * 2048];   // x split: [row][0..1023]=hi, [1024..2047]=lo (K padded)
__device__ __half g_w1h[1024 * H1];               // W1 hi (K padded to 1024)
__device__ __half g_w1l[1024 * H1];               // W1 lo
__device__ __half g_hs[(size_t)N_NODES * 1024];   // h split: [0..511]=hi, [512..1023]=lo
__device__ __half g_w23h[H1 * DG];
__device__ __half g_w23l[H1 * DG];
__device__ float  g_c2[DG];
__device__ float  g_y[(size_t)N_NODES * DG];
__device__ int    g_deg[N_NODES];
__device__ int    g_off[N_NODES];
__device__ int    g_cur[N_NODES];
__device__ int    g_es[N_EDGESC];
__device__ int    g_bsum[128];
__device__ double g_acc;

// ---------------- helpers ----------------
__device__ __forceinline__ uint32_t smem_u32(const void* p) {
    uint32_t a;
    asm("{ .reg .u64 t; cvta.to.shared.u64 t, %1; cvt.u32.u64 %0, t; }" : "=r"(a) : "l"(p));
    return a;
}
#define CP_A16(dst, src, n) \
    asm volatile("cp.async.cg.shared.global [%0], [%1], 16, %2;" :: "r"(dst), "l"(src), "r"(n))
#define CP_COMMIT() asm volatile("cp.async.commit_group;" ::: "memory")
#define CP_WAIT0()  asm volatile("cp.async.wait_group 0;" ::: "memory")

__device__ __forceinline__ void split_h2(float2 v, __half2& hi, __half2& lo) {
    hi = __float22half2_rn(v);
    float2 l = make_float2(v.x - __half2float(__low2half(hi)),
                           v.y - __half2float(__high2half(hi)));
    lo = __float22half2_rn(l);
}

// ---------------- pre-split x ----------------
__global__ void k_splitx(const float* __restrict__ x) {
    for (long long id = (long long)blockIdx.x * blockDim.x + threadIdx.x;
         id < (long long)N_NODES * 512; id += (long long)gridDim.x * blockDim.x) {
        int row = (int)(id >> 9);
        int c2 = (int)(id & 511);
        int col = c2 * 2;
        float2 v = make_float2(0.f, 0.f);
        if (col < SUBJ) v = *reinterpret_cast<const float2*>(&x[(size_t)row * XDIM + col]);
        __half2 hi, lo;
        split_h2(v, hi, lo);
        *reinterpret_cast<__half2*>(&g_xs[(size_t)row * 2048 + col]) = hi;
        *reinterpret_cast<__half2*>(&g_xs[(size_t)row * 2048 + 1024 + col]) = lo;
    }
}

// ---------------- pre-split W1 ----------------
__global__ void k_splitw(const float* __restrict__ W1) {
    int id = blockIdx.x * blockDim.x + threadIdx.x;   // over 1024*256 float2 units
    if (id >= 1024 * 256) return;
    int row = id >> 8;
    int col = (id & 255) * 2;
    float2 v = make_float2(0.f, 0.f);
    if (row < SUBJ) v = *reinterpret_cast<const float2*>(&W1[(size_t)row * H1 + col]);
    __half2 hi, lo;
    split_h2(v, hi, lo);
    *reinterpret_cast<__half2*>(&g_w1h[row * H1 + col]) = hi;
    *reinterpret_cast<__half2*>(&g_w1l[row * H1 + col]) = lo;
}

// ---------------- init ----------------
__global__ void k_init() {
    int i = blockIdx.x * blockDim.x + threadIdx.x;
    if (i < N_NODES) g_deg[i] = 1;
    if (i == 0) g_acc = 0.0;
}

// ---------------- weight fold (writes split fp16) ----------------
__global__ void k_pre(const float* __restrict__ W2, const float* __restrict__ Wg,
                      const float* __restrict__ b2) {
    int k = blockIdx.x;
    int j = threadIdx.x;
    if (k < H1) {
        __shared__ float row[H2];
        for (int m = j; m < H2; m += 128) row[m] = W2[k * H2 + m];
        __syncthreads();
        float acc = 0.f;
        #pragma unroll 4
        for (int m = 0; m < H2; m++) acc += row[m] * Wg[m * DG + j];
        __half h = __float2half_rn(acc);
        g_w23h[k * DG + j] = h;
        g_w23l[k * DG + j] = __float2half_rn(acc - __half2float(h));
    } else {
        float acc = 0.f;
        for (int m = 0; m < H2; m++) acc += b2[m] * Wg[m * DG + j];
        g_c2[j] = acc;
    }
}

// ---------------- degree count ----------------
__global__ void k_deg(const int* __restrict__ ei) {
    for (int e = blockIdx.x * blockDim.x + threadIdx.x; e < N_EDGESC;
         e += gridDim.x * blockDim.x) {
        int dst = ei[N_EDGESC + e];
        dst = min(max(dst, 0), N_NODES - 1);
        atomicAdd(&g_deg[dst], 1);
    }
}

// ---------------- multi-block scan of (deg-1) ----------------
#define SCAN_CHUNK 1024
#define SCAN_NBLK ((N_NODES + SCAN_CHUNK - 1) / SCAN_CHUNK)  // 98

__global__ void k_scan1() {
    __shared__ int wsum[32];
    int i = blockIdx.x * SCAN_CHUNK + threadIdx.x;
    int v = (i < N_NODES) ? (g_deg[i] - 1) : 0;
    #pragma unroll
    for (int o = 16; o; o >>= 1) v += __shfl_down_sync(0xffffffffu, v, o);
    int lane = threadIdx.x & 31, wid = threadIdx.x >> 5;
    if (lane == 0) wsum[wid] = v;
    __syncthreads();
    if (wid == 0) {
        int t = wsum[lane];
        #pragma unroll
        for (int o = 16; o; o >>= 1) t += __shfl_down_sync(0xffffffffu, t, o);
        if (lane == 0) g_bsum[blockIdx.x] = t;
    }
}

__global__ void k_scan2() {
    __shared__ int wtot[4];
    int tid = threadIdx.x, lane = tid & 31, wid = tid >> 5;
    int v = (tid < SCAN_NBLK) ? g_bsum[tid] : 0;
    int s = v;
    #pragma unroll
    for (int o = 1; o < 32; o <<= 1) {
        int t = __shfl_up_sync(0xffffffffu, s, o);
        if (lane >= o) s += t;
    }
    if (lane == 31) wtot[wid] = s;
    __syncthreads();
    int base = 0;
    for (int w = 0; w < wid; w++) base += wtot[w];
    if (tid < SCAN_NBLK) g_bsum[tid] = base + s - v;
}

__global__ void k_scan3() {
    __shared__ int wpre[32];
    int tid = threadIdx.x, lane = tid & 31, wid = tid >> 5;
    int i = blockIdx.x * SCAN_CHUNK + tid;
    int v = (i < N_NODES) ? (g_deg[i] - 1) : 0;
    int s = v;
    #pragma unroll
    for (int o = 1; o < 32; o <<= 1) {
        int t = __shfl_up_sync(0xffffffffu, s, o);
        if (lane >= o) s += t;
    }
    if (lane == 31) wpre[wid] = s;
    __syncthreads();
    if (wid == 0) {
        int t = wpre[lane];
        #pragma unroll
        for (int o = 1; o < 32; o <<= 1) {
            int u = __shfl_up_sync(0xffffffffu, t, o);
            if (lane >= o) t += u;
        }
        wpre[lane] = t;
    }
    __syncthreads();
    int excl = s - v + (wid > 0 ? wpre[wid - 1] : 0) + g_bsum[blockIdx.x];
    if (i < N_NODES) { g_off[i] = excl; g_cur[i] = excl; }
}

// ---------------- CSR fill ----------------
__global__ void k_fill(const int* __restrict__ ei) {
    for (int e = blockIdx.x * blockDim.x + threadIdx.x; e < N_EDGESC;
         e += gridDim.x * blockDim.x) {
        int src = ei[e];
        int dst = ei[N_EDGESC + e];
        src = min(max(src, 0), N_NODES - 1);
        dst = min(max(dst, 0), N_NODES - 1);
        int pos = atomicAdd(&g_cur[dst], 1);
        g_es[pos] = src;
    }
}

// ================= shared GEMM geometry =================
#define G_LDA 40        // fp16 elems (80B rows, 16B-multiple)
#define G_LDB 136       // fp16 elems (272B rows)
#define G_LDC 136
#define SZ_A (128 * G_LDA * 2)   // 10240
#define SZ_B (32 * G_LDB * 2)    //  8704
#define OFF_AL SZ_A
#define OFF_BH (2 * SZ_A)
#define OFF_BL (2 * SZ_A + SZ_B)
#define G_STAGE (2 * SZ_A + 2 * SZ_B)   // 37888
#define G_DYN (2 * G_STAGE)             // 75776

// issue cp.async loads for one k-tile of a split GEMM.
// A: rows [i0,i0+128) of a [rows x (2*Kpad)] half matrix (hi at kcol, lo at Kpad+kcol)
// B: rows [k0,k0+32) of [Kpad x N] hi/lo half matrices, cols [n0, n0+128)
__device__ __forceinline__ void issue_tile(
    char* st, int tid,
    const __half* Asrc, size_t a_stride, int a_rows_left, int kcol, int kpad,
    const __half* Bh, const __half* Bl, int b_stride, int k0, int n0)
{
    const uint32_t ah = smem_u32(st);
    const uint32_t al = ah + OFF_AL;
    const uint32_t bh = ah + OFF_BH;
    const uint32_t bl = ah + OFF_BL;
    #pragma unroll
    for (int p = 0; p < 2; p++) {
        int idx = tid + p * 256;          // 0..511
        int row = idx >> 2;               // 0..127
        int ch = idx & 3;                 // 16B chunk within 64B
        int n = (row < a_rows_left) ? 16 : 0;
        const __half* s = Asrc + (size_t)row * a_stride + kcol + ch * 8;
        CP_A16(ah + row * (G_LDA * 2) + ch * 16, s, n);
        CP_A16(al + row * (G_LDA * 2) + ch * 16, s + kpad, n);
    }
    #pragma unroll
    for (int p = 0; p < 2; p++) {
        int idx = tid + p * 256;          // 0..511
        int row = idx >> 4;               // 0..31
        int ch = idx & 15;                // 16B chunk within 256B
        const __half* sh = Bh + (size_t)(k0 + row) * b_stride + n0 + ch * 8;
        const __half* sl = Bl + (size_t)(k0 + row) * b_stride + n0 + ch * 8;
        CP_A16(bh + row * (G_LDB * 2) + ch * 16, sh, 16);
        CP_A16(bl + row * (G_LDB * 2) + ch * 16, sl, 16);
    }
    CP_COMMIT();
}

__device__ __forceinline__ void mma_tile(
    char* st, int warpM, int warpN,
    wmma::fragment<wmma::accumulator, 16, 16, 16, float> (*acc)[4])
{
    __half (*Ah)[G_LDA] = reinterpret_cast<__half(*)[G_LDA]>(st);
    __half (*Al)[G_LDA] = reinterpret_cast<__half(*)[G_LDA]>(st + OFF_AL);
    __half (*Bh)[G_LDB] = reinterpret_cast<__half(*)[G_LDB]>(st + OFF_BH);
    __half (*Bl)[G_LDB] = reinterpret_cast<__half(*)[G_LDB]>(st + OFF_BL);
    #pragma unroll
    for (int kk = 0; kk < 32; kk += 16) {
        wmma::fragment<wmma::matrix_a, 16, 16, 16, __half, wmma::row_major> afH[2], afL[2];
        #pragma unroll
        for (int m = 0; m < 2; m++) {
            wmma::load_matrix_sync(afH[m], &Ah[warpM * 32 + m * 16][kk], G_LDA);
            wmma::load_matrix_sync(afL[m], &Al[warpM * 32 + m * 16][kk], G_LDA);
        }
        #pragma unroll
        for (int n = 0; n < 4; n++) {
            wmma::fragment<wmma::matrix_b, 16, 16, 16, __half, wmma::row_major> bfH, bfL;
            wmma::load_matrix_sync(bfH, &Bh[kk][warpN * 64 + n * 16], G_LDB);
            wmma::load_matrix_sync(bfL, &Bl[kk][warpN * 64 + n * 16], G_LDB);
            #pragma unroll
            for (int m = 0; m < 2; m++) {
                wmma::mma_sync(acc[m][n], afH[m], bfL, acc[m][n]);
                wmma::mma_sync(acc[m][n], afL[m], bfH, acc[m][n]);
                wmma::mma_sync(acc[m][n], afH[m], bfH, acc[m][n]);
            }
        }
    }
}

// ================= GEMM1: h = relu(x @ W1 + b1), split fp16 out =================
__global__ __launch_bounds__(256) void k_gemm1(const float* __restrict__ b1) {
    extern __shared__ __align__(128) char dyn[];
    const int i0 = blockIdx.x * 128;
    const int n0 = blockIdx.y * 128;
    const int tid = threadIdx.x;
    const int wid = tid >> 5;
    const int warpM = wid & 3, warpN = wid >> 2;
    const int rows_left = N_NODES - i0;

    wmma::fragment<wmma::accumulator, 16, 16, 16, float> acc[2][4];
    #pragma unroll
    for (int m = 0; m < 2; m++)
        #pragma unroll
        for (int n = 0; n < 4; n++) wmma::fill_fragment(acc[m][n], 0.f);

    issue_tile(dyn, tid, g_xs + (size_t)i0 * 2048, 2048, rows_left, 0, 1024,
               g_w1h, g_w1l, H1, 0, n0);

    for (int kt = 0; kt < 32; kt++) {
        const int s = kt & 1;
        CP_WAIT0();
        __syncthreads();
        if (kt + 1 < 32)
            issue_tile(dyn + (s ^ 1) * G_STAGE, tid,
                       g_xs + (size_t)i0 * 2048, 2048, rows_left, (kt + 1) * 32, 1024,
                       g_w1h, g_w1l, H1, (kt + 1) * 32, n0);
        mma_tile(dyn + s * G_STAGE, warpM, warpN, acc);
        __syncthreads();
    }

    // epilogue: smem -> bias+relu -> split fp16 to g_hs
    float (*Cs)[G_LDC] = reinterpret_cast<float(*)[G_LDC]>(dyn);
    #pragma unroll
    for (int m = 0; m < 2; m++)
        #pragma unroll
        for (int n = 0; n < 4; n++)
            wmma::store_matrix_sync(&Cs[warpM * 32 + m * 16][warpN * 64 + n * 16],
                                    acc[m][n], G_LDC, wmma::mem_row_major);
    __syncthreads();
    #pragma unroll
    for (int q = 0; q < 32; q++) {
        int idx = q * 256 + tid;        // over 128x64 half2 pairs
        int r = idx >> 6, c2 = (idx & 63) * 2;
        int gi = i0 + r;
        if (gi < N_NODES) {
            float2 v;
            v.x = fmaxf(Cs[r][c2] + __ldg(&b1[n0 + c2]), 0.f);
            v.y = fmaxf(Cs[r][c2 + 1] + __ldg(&b1[n0 + c2 + 1]), 0.f);
            __half2 hi, lo;
            split_h2(v, hi, lo);
            *reinterpret_cast<__half2*>(&g_hs[(size_t)gi * 1024 + n0 + c2]) = hi;
            *reinterpret_cast<__half2*>(&g_hs[(size_t)gi * 1024 + 512 + n0 + c2]) = lo;
        }
    }
}

// ================= GEMM2: y = dinv*(h @ W23 + demo @ Wg[256:] + c2) =================
__global__ __launch_bounds__(256) void k_gemm2(const float* __restrict__ x,
                                               const float* __restrict__ Wg) {
    extern __shared__ __align__(128) char dyn[];
    __shared__ float demoS[128][10];
    __shared__ float WgbS[10][DG];
    __shared__ float c2S[DG];

    const int i0 = blockIdx.x * 128;
    const int tid = threadIdx.x;
    const int wid = tid >> 5;
    const int warpM = wid & 3, warpN = wid >> 2;
    const int rows_left = N_NODES - i0;

    for (int idx = tid; idx < 128 * 10; idx += 256) {
        int r = idx / 10, t = idx % 10;
        int gi = i0 + r;
        demoS[r][t] = (gi < N_NODES) ? x[(size_t)gi * XDIM + SUBJ + t] : 0.f;
    }
    for (int idx = tid; idx < 10 * DG; idx += 256) {
        int t = idx >> 7, c = idx & 127;
        WgbS[t][c] = Wg[(H2 + t) * DG + c];
    }
    if (tid < DG) c2S[tid] = g_c2[tid];

    wmma::fragment<wmma::accumulator, 16, 16, 16, float> acc[2][4];
    #pragma unroll
    for (int m = 0; m < 2; m++)
        #pragma unroll
        for (int n = 0; n < 4; n++) wmma::fill_fragment(acc[m][n], 0.f);

    issue_tile(dyn, tid, g_hs + (size_t)i0 * 1024, 1024, rows_left, 0, 512,
               g_w23h, g_w23l, DG, 0, 0);

    for (int kt = 0; kt < 16; kt++) {
        const int s = kt & 1;
        CP_WAIT0();
        __syncthreads();
        if (kt + 1 < 16)
            issue_tile(dyn + (s ^ 1) * G_STAGE, tid,
                       g_hs + (size_t)i0 * 1024, 1024, rows_left, (kt + 1) * 32, 512,
                       g_w23h, g_w23l, DG, (kt + 1) * 32, 0);
        mma_tile(dyn + s * G_STAGE, warpM, warpN, acc);
        __syncthreads();
    }

    float (*Cs)[G_LDC] = reinterpret_cast<float(*)[G_LDC]>(dyn);
    #pragma unroll
    for (int m = 0; m < 2; m++)
        #pragma unroll
        for (int n = 0; n < 4; n++)
            wmma::store_matrix_sync(&Cs[warpM * 32 + m * 16][warpN * 64 + n * 16],
                                    acc[m][n], G_LDC, wmma::mem_row_major);
    __syncthreads();
    #pragma unroll
    for (int q = 0; q < 64; q++) {
        int idx = q * 256 + tid;
        int r = idx >> 7, c = idx & 127;
        int gi = i0 + r;
        if (gi < N_NODES) {
            float v = Cs[r][c] + c2S[c];
            #pragma unroll
            for (int t = 0; t < 10; t++) v += demoS[r][t] * WgbS[t][c];
            float dinv = rsqrtf((float)g_deg[gi]);
            g_y[(size_t)gi * DG + c] = dinv * v;
        }
    }
}

// ---------------- gather + fused epilogue ----------------
__global__ __launch_bounds__(256) void k_gather(const float* __restrict__ bg,
                                                const float* __restrict__ Wo) {
    int wid = threadIdx.x >> 5, lane = threadIdx.x & 31;
    int node = blockIdx.x * 8 + wid;
    float dot = 0.f;
    if (node < N_NODES) {
        int deg = g_deg[node];
        int beg = g_off[node];
        int cnt = deg - 1;
        float4 a = *reinterpret_cast<const float4*>(&g_y[(size_t)node * DG + lane * 4]);
        #pragma unroll 4
        for (int j = 0; j < cnt; j++) {
            int s = __ldg(&g_es[beg + j]);
            float4 v = *reinterpret_cast<const float4*>(&g_y[(size_t)s * DG + lane * 4]);
            a.x += v.x; a.y += v.y; a.z += v.z; a.w += v.w;
        }
        float dinv = rsqrtf((float)deg);
        float4 bgv = *reinterpret_cast<const float4*>(&bg[lane * 4]);
        float4 wv = *reinterpret_cast<const float4*>(&Wo[lane * 4]);
        dot += fmaxf(dinv * a.x + bgv.x, 0.f) * wv.x;
        dot += fmaxf(dinv * a.y + bgv.y, 0.f) * wv.y;
        dot += fmaxf(dinv * a.z + bgv.z, 0.f) * wv.z;
        dot += fmaxf(dinv * a.w + bgv.w, 0.f) * wv.w;
    }
    #pragma unroll
    for (int o = 16; o; o >>= 1) dot += __shfl_down_sync(0xffffffffu, dot, o);
    __shared__ float part[8];
    if (lane == 0) part[wid] = dot;
    __syncthreads();
    if (threadIdx.x == 0) {
        float s = 0.f;
        #pragma unroll
        for (int w = 0; w < 8; w++) s += part[w];
        atomicAdd(&g_acc, (double)s);
    }
}

__global__ void k_fin(const float* __restrict__ bo, float* __restrict__ out) {
    out[0] = (float)(g_acc * (1.0 / (double)N_NODES) + (double)bo[0]);
}

// ---------------- launch ----------------
extern "C" void kernel_launch(void* const* d_in, const int* in_sizes, int n_in,
                              void* d_out, int out_size) {
    const float* x  = (const float*)d_in[0];
    const int*   ei = (const int*)d_in[1];
    const float* W1 = (const float*)d_in[2];
    const float* b1 = (const float*)d_in[3];
    const float* W2 = (const float*)d_in[4];
    const float* b2 = (const float*)d_in[5];
    const float* Wg = (const float*)d_in[6];
    const float* bg = (const float*)d_in[7];
    const float* Wo = (const float*)d_in[8];
    const float* bo = (const float*)d_in[9];
    float* out = (float*)d_out;

    cudaFuncSetAttribute(k_gemm1, cudaFuncAttributeMaxDynamicSharedMemorySize, G_DYN);
    cudaFuncSetAttribute(k_gemm2, cudaFuncAttributeMaxDynamicSharedMemorySize, G_DYN);

    k_splitx<<<2048, 256>>>(x);                                   // 1
    k_splitw<<<(1024 * 256 + 255) / 256, 256>>>(W1);              // 2
    k_init<<<(N_NODES + 255) / 256, 256>>>();                     // 3
    k_gemm1<<<dim3((N_NODES + 127) / 128, H1 / 128), 256, G_DYN>>>(b1);  // 4 <- ncu capture slot
    k_deg<<<4096, 256>>>(ei);                                     // 5
    k_scan1<<<SCAN_NBLK, SCAN_CHUNK>>>();                         // 6
    k_scan2<<<1, 128>>>();                                        // 7
    k_scan3<<<SCAN_NBLK, SCAN_CHUNK>>>();                         // 8
    k_fill<<<4096, 256>>>(ei);                                    // 9
    k_pre<<<H1 + 1, 128>>>(W2, Wg, b2);                           // 10
    k_gemm2<<<(N_NODES + 127) / 128, 256, G_DYN>>>(x, Wg);        // 11
    k_gather<<<(N_NODES + 7) / 8, 256>>>(bg, Wo);                 // 12
    k_fin<<<1, 1>>>(bo, out);                                     // 13
}